// round 1
// baseline (speedup 1.0000x reference)
#include <cuda_runtime.h>
#include <cuda_bf16.h>
#include <math.h>

// Problem constants
#define BB 4
#define LL 4096
#define CC 512
#define HH 16
#define HD 32
#define KW 13           // kernel (window) size
#define KH 6            // KW/2
#define NRPB 25         // 2*KW-1
#define ML (BB*LL)      // 16384 rows

// Scratch (allocation-free rule: __device__ globals)
__device__ float g_qkv[(size_t)ML * (3 * CC)];   // 96 MB: [b*L+l, t*512 + h*32 + d]
__device__ float g_attn[(size_t)ML * CC];        // 32 MB: [b*L+l, h*32 + d]

// ---------------------------------------------------------------------------
// SGEMM: C = A(MxK) * B(KxN) + bias, row-major, 128x128 tile, 8x8 per thread
// M % 128 == 0, N % 128 == 0, K % 8 == 0 (all true here)
// ---------------------------------------------------------------------------
__global__ __launch_bounds__(256, 2)
void sgemm_bias_kernel(const float* __restrict__ A, const float* __restrict__ B,
                       const float* __restrict__ bias, float* __restrict__ C,
                       int M, int N, int K)
{
    constexpr int BM = 128, BN = 128, BK = 8;
    __shared__ float As[BK][BM];
    __shared__ float Bs[BK][BN];

    const int tid = threadIdx.x;          // 0..255
    const int bx = blockIdx.x;            // N tile
    const int by = blockIdx.y;            // M tile

    // Global-load assignments (one float4 each per tile step)
    const int arow = tid >> 1;            // 0..127
    const int acol = (tid & 1) << 2;      // 0 or 4
    const int brow = tid >> 5;            // 0..7
    const int bcol = (tid & 31) << 2;     // 0..124

    const float* Ag = A + (size_t)(by * BM + arow) * K + acol;
    const float* Bg = B + (size_t)brow * N + (size_t)bx * BN + bcol;

    const int tx = tid & 15;              // 0..15 -> col groups
    const int ty = tid >> 4;              // 0..15 -> row groups

    float acc[8][8];
    #pragma unroll
    for (int i = 0; i < 8; i++)
        #pragma unroll
        for (int j = 0; j < 8; j++) acc[i][j] = 0.f;

    for (int k0 = 0; k0 < K; k0 += BK) {
        float4 av = *(const float4*)(Ag + k0);
        float4 bv = *(const float4*)(Bg + (size_t)k0 * N);

        As[acol + 0][arow] = av.x;
        As[acol + 1][arow] = av.y;
        As[acol + 2][arow] = av.z;
        As[acol + 3][arow] = av.w;
        *(float4*)&Bs[brow][bcol] = bv;
        __syncthreads();

        #pragma unroll
        for (int k = 0; k < BK; k++) {
            float a[8], b[8];
            *(float4*)&a[0] = *(const float4*)&As[k][ty * 4];
            *(float4*)&a[4] = *(const float4*)&As[k][64 + ty * 4];
            *(float4*)&b[0] = *(const float4*)&Bs[k][tx * 4];
            *(float4*)&b[4] = *(const float4*)&Bs[k][64 + tx * 4];
            #pragma unroll
            for (int i = 0; i < 8; i++)
                #pragma unroll
                for (int j = 0; j < 8; j++)
                    acc[i][j] = fmaf(a[i], b[j], acc[i][j]);
        }
        __syncthreads();
    }

    // Epilogue: add bias, store (two float4 per row-slot)
    const int c0 = bx * BN + tx * 4;
    const int c1 = c0 + 64;
    float4 bia0 = *(const float4*)(bias + c0);
    float4 bia1 = *(const float4*)(bias + c1);

    #pragma unroll
    for (int i = 0; i < 8; i++) {
        int row = by * BM + ((i < 4) ? (ty * 4 + i) : (64 + ty * 4 + (i - 4)));
        float* Crow = C + (size_t)row * N;
        float4 o0 = make_float4(acc[i][0] + bia0.x, acc[i][1] + bia0.y,
                                acc[i][2] + bia0.z, acc[i][3] + bia0.w);
        float4 o1 = make_float4(acc[i][4] + bia1.x, acc[i][5] + bia1.y,
                                acc[i][6] + bia1.z, acc[i][7] + bia1.w);
        *(float4*)(Crow + c0) = o0;
        *(float4*)(Crow + c1) = o1;
    }
}

// ---------------------------------------------------------------------------
// Neighborhood attention: one warp per (b, h, l); lane = head-dim element d.
// Reads q/k/v from g_qkv, writes [b*L+l, h*32+d] into g_attn.
// ---------------------------------------------------------------------------
__global__ __launch_bounds__(256)
void natten1d_kernel(const float* __restrict__ rpb)
{
    const int gw = (blockIdx.x * blockDim.x + threadIdx.x) >> 5;
    const int lane = threadIdx.x & 31;
    // gw in [0, B*H*L)
    const int l = gw & (LL - 1);
    const int h = (gw >> 12) & (HH - 1);
    const int b = gw >> 16;

    int ni = l - KH;
    if (ni < 0) ni = 0;
    if (ni > LL - KW) ni = LL - KW;
    const int roff = ni - l + (KW - 1);

    const float* base = g_qkv + (size_t)b * LL * (3 * CC);
    const float scale = 0.17677669529663687f;  // 1/sqrt(32)

    const float qd = base[(size_t)l * (3 * CC) + h * HD + lane] * scale;

    const float* rpb_h = rpb + h * NRPB;

    float scores[KW];
    float smax = -1e30f;
    #pragma unroll
    for (int j = 0; j < KW; j++) {
        float kd = base[(size_t)(ni + j) * (3 * CC) + CC + h * HD + lane];
        float s = qd * kd;
        #pragma unroll
        for (int o = 16; o > 0; o >>= 1)
            s += __shfl_xor_sync(0xffffffffu, s, o);
        s += rpb_h[roff + j];
        scores[j] = s;
        smax = fmaxf(smax, s);
    }

    float ssum = 0.f;
    #pragma unroll
    for (int j = 0; j < KW; j++) {
        scores[j] = __expf(scores[j] - smax);
        ssum += scores[j];
    }
    const float inv = 1.f / ssum;

    float acc = 0.f;
    #pragma unroll
    for (int j = 0; j < KW; j++) {
        float vd = base[(size_t)(ni + j) * (3 * CC) + 2 * CC + h * HD + lane];
        acc = fmaf(scores[j], vd, acc);
    }
    acc *= inv;

    g_attn[(size_t)(b * LL + l) * CC + h * HD + lane] = acc;
}

// ---------------------------------------------------------------------------
extern "C" void kernel_launch(void* const* d_in, const int* in_sizes, int n_in,
                              void* d_out, int out_size)
{
    const float* x      = (const float*)d_in[0];  // [4,4096,512]
    const float* qkv_w  = (const float*)d_in[1];  // [512,1536]
    const float* qkv_b  = (const float*)d_in[2];  // [1536]
    const float* rpb    = (const float*)d_in[3];  // [16,25]
    const float* proj_w = (const float*)d_in[4];  // [512,512]
    const float* proj_b = (const float*)d_in[5];  // [512]
    float* out = (float*)d_out;                   // [4,4096,512]

    float* qkv;  cudaGetSymbolAddress((void**)&qkv,  g_qkv);
    float* attn; cudaGetSymbolAddress((void**)&attn, g_attn);

    // 1) QKV GEMM: [16384,512] x [512,1536]
    {
        dim3 grid(1536 / 128, ML / 128);
        sgemm_bias_kernel<<<grid, 256>>>(x, qkv_w, qkv_b, qkv, ML, 3 * CC, CC);
    }

    // 2) Neighborhood attention: B*H*L warps
    {
        int total_warps = BB * HH * LL;            // 262144
        int blocks = total_warps * 32 / 256;       // 32768
        natten1d_kernel<<<blocks, 256>>>(rpb);
    }

    // 3) Projection GEMM: [16384,512] x [512,512]
    {
        dim3 grid(CC / 128, ML / 128);
        sgemm_bias_kernel<<<grid, 256>>>(attn, proj_w, proj_b, out, ML, CC, CC);
    }
}

// round 3
// speedup vs baseline: 1.1773x; 1.1773x over previous
#include <cuda_runtime.h>
#include <cuda_bf16.h>
#include <cstdint>
#include <math.h>

// Problem constants
#define BB 4
#define LL 4096
#define CC 512
#define HH 16
#define HD 32
#define KW 13
#define KH 6
#define NRPB 25
#define ML (BB*LL)

// Scratch
__device__ float g_qkv[(size_t)ML * (3 * CC)];
__device__ float g_attn[(size_t)ML * CC];

// ---------------------------------------------------------------------------
// 3xTF32 tensor-core GEMM: C = A(MxK) x B(KxN) + bias. Row-major.
// Each operand split a = hi + lo (tf32 each); D += hi*hi + hi*lo + lo*hi.
// Precision ~fp32 (lo*lo term ~2^-22 relative, dropped).
// 128x128x16 tiles, 256 threads (8 warps, warp tile 64x32), cp.async dbuf.
// ---------------------------------------------------------------------------
#define BM 128
#define BN 128
#define BKT 16
#define ASTRIDE (BKT + 4)    // 20
#define BSTRIDE (BN + 8)     // 136

__device__ __forceinline__ uint32_t sptr(const void* p) {
    return (uint32_t)__cvta_generic_to_shared(p);
}
__device__ __forceinline__ void cp16(uint32_t s, const void* g) {
    asm volatile("cp.async.cg.shared.global [%0], [%1], 16;\n" :: "r"(s), "l"(g));
}
__device__ __forceinline__ void cp_commit() {
    asm volatile("cp.async.commit_group;\n" ::: "memory");
}
__device__ __forceinline__ void cp_wait0() {
    asm volatile("cp.async.wait_group 0;\n" ::: "memory");
}
__device__ __forceinline__ void mma_tf32(float* c, const uint32_t* a, const uint32_t* b) {
    asm volatile(
        "mma.sync.aligned.m16n8k8.row.col.f32.tf32.tf32.f32 "
        "{%0,%1,%2,%3}, {%4,%5,%6,%7}, {%8,%9}, {%0,%1,%2,%3};\n"
        : "+f"(c[0]), "+f"(c[1]), "+f"(c[2]), "+f"(c[3])
        : "r"(a[0]), "r"(a[1]), "r"(a[2]), "r"(a[3]), "r"(b[0]), "r"(b[1]));
}
// Split fp32 into tf32 hi + tf32 lo (residual)
__device__ __forceinline__ void tf32x2(float x, uint32_t& hi, uint32_t& lo) {
    uint32_t h;
    asm("cvt.rna.tf32.f32 %0, %1;" : "=r"(h) : "f"(x));
    float l = x - __uint_as_float(h);
    uint32_t lr;
    asm("cvt.rna.tf32.f32 %0, %1;" : "=r"(lr) : "f"(l));
    hi = h; lo = lr;
}

__global__ __launch_bounds__(256, 2)
void tf32x3_gemm_bias(const float* __restrict__ A, const float* __restrict__ B,
                      const float* __restrict__ bias, float* __restrict__ C,
                      int M, int N, int K)
{
    __shared__ float As[2][BM][ASTRIDE];
    __shared__ float Bs[2][BKT][BSTRIDE];

    const int tid  = threadIdx.x;
    const int warp = tid >> 5;
    const int lane = tid & 31;
    const int wm   = warp & 1;
    const int wn   = warp >> 1;
    const int gid  = lane >> 2;   // 0..7
    const int tg   = lane & 3;    // 0..3

    const int bm0 = blockIdx.y * BM;
    const int bn0 = blockIdx.x * BN;

    const int arow = tid >> 1;
    const int acol = (tid & 1) * 8;
    const int brow = tid >> 4;
    const int bcol = (tid & 15) * 4;

    const float* Ag = A + (size_t)(bm0 + arow) * K + acol;
    const float* Bg = B + (size_t)brow * N + bn0 + bcol;

    float acc[4][4][4];
    #pragma unroll
    for (int mt = 0; mt < 4; mt++)
        #pragma unroll
        for (int nt = 0; nt < 4; nt++)
            #pragma unroll
            for (int c = 0; c < 4; c++) acc[mt][nt][c] = 0.f;

    const int nT = K / BKT;

    cp16(sptr(&As[0][arow][acol]),     Ag);
    cp16(sptr(&As[0][arow][acol + 4]), Ag + 4);
    cp16(sptr(&Bs[0][brow][bcol]),      Bg);
    cp16(sptr(&Bs[0][brow][bcol + 64]), Bg + 64);
    cp_commit();

    for (int t = 0; t < nT; t++) {
        cp_wait0();
        __syncthreads();
        const int cur = t & 1;

        if (t + 1 < nT) {
            const int nxt = cur ^ 1;
            const float* Ag2 = Ag + (t + 1) * BKT;
            const float* Bg2 = Bg + (size_t)(t + 1) * BKT * N;
            cp16(sptr(&As[nxt][arow][acol]),     Ag2);
            cp16(sptr(&As[nxt][arow][acol + 4]), Ag2 + 4);
            cp16(sptr(&Bs[nxt][brow][bcol]),      Bg2);
            cp16(sptr(&Bs[nxt][brow][bcol + 64]), Bg2 + 64);
            cp_commit();
        }

        #pragma unroll
        for (int ks = 0; ks < 2; ks++) {
            const int kb = ks * 8;

            // B fragments, hi+lo
            uint32_t bh[4][2], bl[4][2];
            #pragma unroll
            for (int nt = 0; nt < 4; nt++) {
                const int col = wn * 32 + nt * 8 + gid;
                tf32x2(Bs[cur][kb + tg    ][col], bh[nt][0], bl[nt][0]);
                tf32x2(Bs[cur][kb + tg + 4][col], bh[nt][1], bl[nt][1]);
            }

            #pragma unroll
            for (int mt = 0; mt < 4; mt++) {
                const int row = wm * 64 + mt * 16;
                uint32_t ah[4], al[4];
                tf32x2(As[cur][row + gid    ][kb + tg    ], ah[0], al[0]);
                tf32x2(As[cur][row + gid + 8][kb + tg    ], ah[1], al[1]);
                tf32x2(As[cur][row + gid    ][kb + tg + 4], ah[2], al[2]);
                tf32x2(As[cur][row + gid + 8][kb + tg + 4], ah[3], al[3]);

                #pragma unroll
                for (int nt = 0; nt < 4; nt++) {
                    mma_tf32(acc[mt][nt], ah, bl[nt]);   // hi*lo
                    mma_tf32(acc[mt][nt], al, bh[nt]);   // lo*hi
                    mma_tf32(acc[mt][nt], ah, bh[nt]);   // hi*hi
                }
            }
        }
    }

    #pragma unroll
    for (int nt = 0; nt < 4; nt++) {
        const int col = bn0 + wn * 32 + nt * 8 + tg * 2;
        const float2 bv = *(const float2*)(bias + col);
        #pragma unroll
        for (int mt = 0; mt < 4; mt++) {
            const int r0 = bm0 + wm * 64 + mt * 16 + gid;
            float2 o0 = make_float2(acc[mt][nt][0] + bv.x, acc[mt][nt][1] + bv.y);
            float2 o1 = make_float2(acc[mt][nt][2] + bv.x, acc[mt][nt][3] + bv.y);
            *(float2*)(C + (size_t)r0 * N + col)       = o0;
            *(float2*)(C + (size_t)(r0 + 8) * N + col) = o1;
        }
    }
}

// ---------------------------------------------------------------------------
// Neighborhood attention, smem-tiled (unchanged; pure fp32)
// ---------------------------------------------------------------------------
#define LTILE 128
#define WROWS (LTILE + KW - 1)   // 140

__global__ __launch_bounds__(256)
void natten1d_smem_kernel(const float* __restrict__ rpb)
{
    __shared__ float sk[WROWS][HD];
    __shared__ float sv[WROWS][HD];
    __shared__ float srpb[NRPB];

    const int tid  = threadIdx.x;
    const int warp = tid >> 5;
    const int lane = tid & 31;

    const int l0 = blockIdx.x * LTILE;
    const int h  = blockIdx.y;
    const int b  = blockIdx.z;

    const int base = l0 - KH;

    const float* qbase = g_qkv + (size_t)b * LL * (3 * CC) + h * HD;
    const float* kbase = qbase + CC;
    const float* vbase = qbase + 2 * CC;

    if (tid < NRPB) srpb[tid] = rpb[h * NRPB + tid];

    for (int r = warp; r < WROWS; r += 8) {
        const int gr = base + r;
        if (gr >= 0 && gr < LL) {
            sk[r][lane] = kbase[(size_t)gr * (3 * CC) + lane];
            sv[r][lane] = vbase[(size_t)gr * (3 * CC) + lane];
        }
    }
    __syncthreads();

    const float scale = 0.17677669529663687f;

    for (int i = 0; i < 16; i++) {
        const int l = l0 + warp * 16 + i;

        int ni = l - KH;
        if (ni < 0) ni = 0;
        if (ni > LL - KW) ni = LL - KW;
        const int roff = ni - l + (KW - 1);
        const int s0 = ni - base;

        const float qd = qbase[(size_t)l * (3 * CC) + lane] * scale;

        float scores[KW];
        float smax = -1e30f;
        #pragma unroll
        for (int j = 0; j < KW; j++) {
            float s = qd * sk[s0 + j][lane];
            #pragma unroll
            for (int o = 16; o > 0; o >>= 1)
                s += __shfl_xor_sync(0xffffffffu, s, o);
            s += srpb[roff + j];
            scores[j] = s;
            smax = fmaxf(smax, s);
        }

        float ssum = 0.f;
        #pragma unroll
        for (int j = 0; j < KW; j++) {
            scores[j] = __expf(scores[j] - smax);
            ssum += scores[j];
        }
        const float inv = 1.f / ssum;

        float accv = 0.f;
        #pragma unroll
        for (int j = 0; j < KW; j++)
            accv = fmaf(scores[j], sv[s0 + j][lane], accv);
        accv *= inv;

        g_attn[(size_t)(b * LL + l) * CC + h * HD + lane] = accv;
    }
}

// ---------------------------------------------------------------------------
extern "C" void kernel_launch(void* const* d_in, const int* in_sizes, int n_in,
                              void* d_out, int out_size)
{
    const float* x      = (const float*)d_in[0];
    const float* qkv_w  = (const float*)d_in[1];
    const float* qkv_b  = (const float*)d_in[2];
    const float* rpb    = (const float*)d_in[3];
    const float* proj_w = (const float*)d_in[4];
    const float* proj_b = (const float*)d_in[5];
    float* out = (float*)d_out;

    float* qkv;  cudaGetSymbolAddress((void**)&qkv,  g_qkv);
    float* attn; cudaGetSymbolAddress((void**)&attn, g_attn);

    {
        dim3 grid((3 * CC) / BN, ML / BM);
        tf32x3_gemm_bias<<<grid, 256>>>(x, qkv_w, qkv_b, qkv, ML, 3 * CC, CC);
    }
    {
        dim3 grid(LL / LTILE, HH, BB);
        natten1d_smem_kernel<<<grid, 256>>>(rpb);
    }
    {
        dim3 grid(CC / BN, ML / BM);
        tf32x3_gemm_bias<<<grid, 256>>>(attn, proj_w, proj_b, out, ML, CC, CC);
    }
}

// round 5
// speedup vs baseline: 1.9346x; 1.6433x over previous
#include <cuda_runtime.h>
#include <cuda_bf16.h>
#include <cstdint>
#include <math.h>

// Problem constants
#define BBX 4
#define LLX 4096
#define CCX 512
#define HHX 16
#define HDX 32
#define KWX 13
#define KHX 6
#define NRPBX 25
#define MLX (BBX*LLX)          // 16384
#define KK  512

// ---------------------------------------------------------------------------
// Global scratch
// ---------------------------------------------------------------------------
__device__ float g_qkv[(size_t)MLX * (3 * CCX)];             // QKV output fp32
__device__ __nv_bfloat16 g_xa_hi[(size_t)MLX * CCX];         // x split
__device__ __nv_bfloat16 g_xa_lo[(size_t)MLX * CCX];
__device__ __nv_bfloat16 g_at_hi[(size_t)MLX * CCX];         // attn out split
__device__ __nv_bfloat16 g_at_lo[(size_t)MLX * CCX];
__device__ __nv_bfloat16 g_w1_hi[(size_t)(3*CCX) * CCX];     // qkv_w^T [1536,512]
__device__ __nv_bfloat16 g_w1_lo[(size_t)(3*CCX) * CCX];
__device__ __nv_bfloat16 g_w2_hi[(size_t)CCX * CCX];         // proj_w^T [512,512]
__device__ __nv_bfloat16 g_w2_lo[(size_t)CCX * CCX];

// ---------------------------------------------------------------------------
// Helpers
// ---------------------------------------------------------------------------
__device__ __forceinline__ uint32_t sptr(const void* p) {
    return (uint32_t)__cvta_generic_to_shared(p);
}
__device__ __forceinline__ void cp16(uint32_t s, const void* g) {
    asm volatile("cp.async.cg.shared.global [%0], [%1], 16;\n" :: "r"(s), "l"(g));
}
__device__ __forceinline__ void cp_commit() {
    asm volatile("cp.async.commit_group;\n" ::: "memory");
}
__device__ __forceinline__ void cp_wait0() {
    asm volatile("cp.async.wait_group 0;\n" ::: "memory");
}
__device__ __forceinline__ void mma_bf16(float* c, const uint32_t* a, const uint32_t* b) {
    asm volatile(
        "mma.sync.aligned.m16n8k16.row.col.f32.bf16.bf16.f32 "
        "{%0,%1,%2,%3}, {%4,%5,%6,%7}, {%8,%9}, {%0,%1,%2,%3};\n"
        : "+f"(c[0]), "+f"(c[1]), "+f"(c[2]), "+f"(c[3])
        : "r"(a[0]), "r"(a[1]), "r"(a[2]), "r"(a[3]), "r"(b[0]), "r"(b[1]));
}
__device__ __forceinline__ void bf16split(float x, __nv_bfloat16& h, __nv_bfloat16& l) {
    h = __float2bfloat16(x);
    l = __float2bfloat16(x - __bfloat162float(h));
}

// ---------------------------------------------------------------------------
// bf16x3 tensor-core GEMM: C[M,N] = (Ahi+Alo)[M,512] x ((Bhi+Blo)[N,512])^T + bias
// 128x128 CTA tile, BK=32 bf16 per stage, 2-stage cp.async, warp tile 64x32.
// Per k16 step: 3 MMAs (hh, hl, lh) -> ~fp32 precision (lo*lo ~2^-18 dropped).
// ---------------------------------------------------------------------------
#define RSTR 40                      // smem row stride in bf16 (80 B, conflict-free)
#define TILE_B (128u * RSTR * 2u)    // 10240 B per operand tile
#define STAGE_B (4u * TILE_B)        // 40960 B
#define GEMM_SMEM (2u * STAGE_B)     // 81920 B

__global__ __launch_bounds__(256, 2)
void bf16x3_gemm(const __nv_bfloat16* __restrict__ Ahi, const __nv_bfloat16* __restrict__ Alo,
                 const __nv_bfloat16* __restrict__ Bhi, const __nv_bfloat16* __restrict__ Blo,
                 const float* __restrict__ bias, float* __restrict__ C, int N)
{
    extern __shared__ char smem[];
    const uint32_t sb = sptr(smem);

    const int tid  = threadIdx.x;
    const int warp = tid >> 5;
    const int lane = tid & 31;
    const int wm   = warp & 1;     // 64-row slab
    const int wn   = warp >> 1;    // 32-col slab
    const int gid  = lane >> 2;    // 0..7
    const int tg   = lane & 3;     // 0..3

    const int bm0 = blockIdx.y * 128;
    const int bn0 = blockIdx.x * 128;

    // loader role: 4 groups of 64 threads, one operand tile each
    const int which = tid >> 6;     // 0=Ahi 1=Alo 2=Bhi 3=Blo
    const int g     = tid & 63;
    const __nv_bfloat16* src = (which == 0) ? Ahi : (which == 1) ? Alo
                             : (which == 2) ? Bhi : Blo;
    const int row0 = (which < 2) ? bm0 : bn0;
    const __nv_bfloat16* gsrc = src + (size_t)row0 * KK;
    const uint32_t tbase = sb + (uint32_t)which * TILE_B;

    #define LOADCHUNK(c, bufb) do { \
        const __nv_bfloat16* gp0 = gsrc + (c) * 32; \
        const uint32_t sm0 = tbase + (bufb) * STAGE_B; \
        _Pragma("unroll") \
        for (int i_ = 0; i_ < 8; i_++) { \
            int u_ = i_ * 64 + g; \
            int row_ = u_ >> 2; \
            int c16_ = u_ & 3; \
            cp16(sm0 + (uint32_t)(row_ * (RSTR * 2) + c16_ * 16), \
                 gp0 + (size_t)row_ * KK + c16_ * 8); \
        } \
        cp_commit(); \
    } while (0)

    float acc[4][4][4];
    #pragma unroll
    for (int mt = 0; mt < 4; mt++)
        #pragma unroll
        for (int nt = 0; nt < 4; nt++)
            #pragma unroll
            for (int c = 0; c < 4; c++) acc[mt][nt][c] = 0.f;

    const int nT = KK / 32;          // 16 chunks

    LOADCHUNK(0, 0);

    for (int t = 0; t < nT; t++) {
        cp_wait0();
        __syncthreads();
        const int cur = t & 1;

        if (t + 1 < nT) LOADCHUNK(t + 1, cur ^ 1);

        const char* stage = smem + cur * STAGE_B;
        const char* pAh = stage;
        const char* pAl = stage + TILE_B;
        const char* pBh = stage + 2 * TILE_B;
        const char* pBl = stage + 3 * TILE_B;

        #pragma unroll
        for (int ks = 0; ks < 2; ks++) {
            const int kb = ks * 32 + tg * 4;     // byte offset of this thread's k-pair

            uint32_t bh[4][2], bl[4][2];
            #pragma unroll
            for (int nt = 0; nt < 4; nt++) {
                const int col = wn * 32 + nt * 8 + gid;
                const int o = col * (RSTR * 2) + kb;
                bh[nt][0] = *(const uint32_t*)(pBh + o);
                bh[nt][1] = *(const uint32_t*)(pBh + o + 16);
                bl[nt][0] = *(const uint32_t*)(pBl + o);
                bl[nt][1] = *(const uint32_t*)(pBl + o + 16);
            }

            #pragma unroll
            for (int mt = 0; mt < 4; mt++) {
                const int r0 = (wm * 64 + mt * 16 + gid) * (RSTR * 2) + kb;
                const int r1 = r0 + 8 * (RSTR * 2);
                uint32_t ah[4], al[4];
                ah[0] = *(const uint32_t*)(pAh + r0);
                ah[1] = *(const uint32_t*)(pAh + r1);
                ah[2] = *(const uint32_t*)(pAh + r0 + 16);
                ah[3] = *(const uint32_t*)(pAh + r1 + 16);
                al[0] = *(const uint32_t*)(pAl + r0);
                al[1] = *(const uint32_t*)(pAl + r1);
                al[2] = *(const uint32_t*)(pAl + r0 + 16);
                al[3] = *(const uint32_t*)(pAl + r1 + 16);

                #pragma unroll
                for (int nt = 0; nt < 4; nt++) {
                    mma_bf16(acc[mt][nt], ah, bh[nt]);   // hi*hi
                    mma_bf16(acc[mt][nt], ah, bl[nt]);   // hi*lo
                    mma_bf16(acc[mt][nt], al, bh[nt]);   // lo*hi
                }
            }
        }
        __syncthreads();
    }
    #undef LOADCHUNK

    // epilogue: + bias, float2 stores
    #pragma unroll
    for (int nt = 0; nt < 4; nt++) {
        const int col = bn0 + wn * 32 + nt * 8 + tg * 2;
        const float2 bv = *(const float2*)(bias + col);
        #pragma unroll
        for (int mt = 0; mt < 4; mt++) {
            const int r0 = bm0 + wm * 64 + mt * 16 + gid;
            float2 o0 = make_float2(acc[mt][nt][0] + bv.x, acc[mt][nt][1] + bv.y);
            float2 o1 = make_float2(acc[mt][nt][2] + bv.x, acc[mt][nt][3] + bv.y);
            *(float2*)(C + (size_t)r0 * N + col)       = o0;
            *(float2*)(C + (size_t)(r0 + 8) * N + col) = o1;
        }
    }
}

// ---------------------------------------------------------------------------
// Elementwise split to bf16 hi/lo (n multiple of 4)
// ---------------------------------------------------------------------------
__global__ __launch_bounds__(256)
void split_kernel(const float* __restrict__ in, __nv_bfloat16* __restrict__ hi,
                  __nv_bfloat16* __restrict__ lo, int n4)
{
    int i = blockIdx.x * 256 + threadIdx.x;
    if (i >= n4) return;
    float4 v = ((const float4*)in)[i];
    __nv_bfloat16 h0, h1, h2, h3, l0, l1, l2, l3;
    bf16split(v.x, h0, l0); bf16split(v.y, h1, l1);
    bf16split(v.z, h2, l2); bf16split(v.w, h3, l3);
    __nv_bfloat162 hp0 = __nv_bfloat162(h0, h1), hp1 = __nv_bfloat162(h2, h3);
    __nv_bfloat162 lp0 = __nv_bfloat162(l0, l1), lp1 = __nv_bfloat162(l2, l3);
    ((uint2*)hi)[i] = make_uint2(*(uint32_t*)&hp0, *(uint32_t*)&hp1);
    ((uint2*)lo)[i] = make_uint2(*(uint32_t*)&lp0, *(uint32_t*)&lp1);
}

// ---------------------------------------------------------------------------
// Transpose + split: w[512, Ndim] -> hi/lo [Ndim, 512] bf16
// ---------------------------------------------------------------------------
__global__ __launch_bounds__(256)
void splitT_kernel(const float* __restrict__ w, __nv_bfloat16* __restrict__ hi,
                   __nv_bfloat16* __restrict__ lo, int Ndim)
{
    __shared__ float t[32][33];
    const int k0 = blockIdx.x * 32;
    const int n0 = blockIdx.y * 32;
    const int tx = threadIdx.x, ty = threadIdx.y;
    #pragma unroll
    for (int r = 0; r < 32; r += 8)
        t[ty + r][tx] = w[(size_t)(k0 + ty + r) * Ndim + n0 + tx];
    __syncthreads();
    #pragma unroll
    for (int r = 0; r < 32; r += 8) {
        float v = t[tx][ty + r];     // = w[k0+tx][n0+ty+r]
        __nv_bfloat16 h, l;
        bf16split(v, h, l);
        const size_t idx = (size_t)(n0 + ty + r) * KK + k0 + tx;
        hi[idx] = h;
        lo[idx] = l;
    }
}

// ---------------------------------------------------------------------------
// Neighborhood attention: thread-per-l, stride-33 smem, writes bf16 split out
// ---------------------------------------------------------------------------
#define LT 128
#define WR (LT + KWX - 1)       // 140
#define SSTR 33

__global__ __launch_bounds__(128)
void natten1d_kernel(const float* __restrict__ rpb)
{
    __shared__ float sk[WR * SSTR];
    __shared__ float sv[WR * SSTR];
    __shared__ float srpb[NRPBX];

    const int tid  = threadIdx.x;
    const int warp = tid >> 5;
    const int lane = tid & 31;
    const int l0 = blockIdx.x * LT;
    const int h  = blockIdx.y;
    const int b  = blockIdx.z;
    const int base = l0 - KHX;

    const float* qb = g_qkv + (size_t)b * LLX * (3 * CCX) + h * HDX;
    const float* kb = qb + CCX;
    const float* vb = qb + 2 * CCX;

    if (tid < NRPBX) srpb[tid] = rpb[h * NRPBX + tid];

    for (int r = warp; r < WR; r += 4) {
        const int gr = base + r;
        if (gr >= 0 && gr < LLX) {
            sk[r * SSTR + lane] = kb[(size_t)gr * (3 * CCX) + lane];
            sv[r * SSTR + lane] = vb[(size_t)gr * (3 * CCX) + lane];
        }
    }
    __syncthreads();

    const int l = l0 + tid;
    int ni = l - KHX;
    if (ni < 0) ni = 0;
    if (ni > LLX - KWX) ni = LLX - KWX;
    const int roff = ni - l + (KWX - 1);
    const int s0 = ni - base;

    const float scale = 0.17677669529663687f;
    float q[HDX];
    {
        const float* qp = qb + (size_t)l * (3 * CCX);
        #pragma unroll
        for (int d4 = 0; d4 < HDX; d4 += 4) {
            float4 v = *(const float4*)(qp + d4);
            q[d4 + 0] = v.x * scale; q[d4 + 1] = v.y * scale;
            q[d4 + 2] = v.z * scale; q[d4 + 3] = v.w * scale;
        }
    }

    float sc[KWX];
    float smax = -1e30f;
    #pragma unroll
    for (int j = 0; j < KWX; j++) {
        const float* kr = &sk[(s0 + j) * SSTR];
        float s = 0.f;
        #pragma unroll
        for (int d = 0; d < HDX; d++) s = fmaf(q[d], kr[d], s);
        s += srpb[roff + j];
        sc[j] = s;
        smax = fmaxf(smax, s);
    }
    float ssum = 0.f;
    #pragma unroll
    for (int j = 0; j < KWX; j++) {
        sc[j] = __expf(sc[j] - smax);
        ssum += sc[j];
    }
    const float inv = 1.f / ssum;

    float acc[HDX];
    #pragma unroll
    for (int d = 0; d < HDX; d++) acc[d] = 0.f;
    #pragma unroll
    for (int j = 0; j < KWX; j++) {
        const float* vr = &sv[(s0 + j) * SSTR];
        const float p = sc[j];
        #pragma unroll
        for (int d = 0; d < HDX; d++) acc[d] = fmaf(p, vr[d], acc[d]);
    }

    __nv_bfloat16* oh = g_at_hi + (size_t)(b * LLX + l) * CCX + h * HDX;
    __nv_bfloat16* ol = g_at_lo + (size_t)(b * LLX + l) * CCX + h * HDX;
    #pragma unroll
    for (int d2 = 0; d2 < HDX; d2 += 2) {
        __nv_bfloat16 h0, h1, l0b, l1b;
        bf16split(acc[d2 + 0] * inv, h0, l0b);
        bf16split(acc[d2 + 1] * inv, h1, l1b);
        __nv_bfloat162 hp = __nv_bfloat162(h0, h1);
        __nv_bfloat162 lp = __nv_bfloat162(l0b, l1b);
        *(uint32_t*)(oh + d2) = *(uint32_t*)&hp;
        *(uint32_t*)(ol + d2) = *(uint32_t*)&lp;
    }
}

// ---------------------------------------------------------------------------
extern "C" void kernel_launch(void* const* d_in, const int* in_sizes, int n_in,
                              void* d_out, int out_size)
{
    const float* x      = (const float*)d_in[0];
    const float* qkv_w  = (const float*)d_in[1];
    const float* qkv_b  = (const float*)d_in[2];
    const float* rpb    = (const float*)d_in[3];
    const float* proj_w = (const float*)d_in[4];
    const float* proj_b = (const float*)d_in[5];
    float* out = (float*)d_out;

    float* qkv;
    __nv_bfloat16 *xh, *xl, *ah, *al, *w1h, *w1l, *w2h, *w2l;
    cudaGetSymbolAddress((void**)&qkv, g_qkv);
    cudaGetSymbolAddress((void**)&xh,  g_xa_hi);
    cudaGetSymbolAddress((void**)&xl,  g_xa_lo);
    cudaGetSymbolAddress((void**)&ah,  g_at_hi);
    cudaGetSymbolAddress((void**)&al,  g_at_lo);
    cudaGetSymbolAddress((void**)&w1h, g_w1_hi);
    cudaGetSymbolAddress((void**)&w1l, g_w1_lo);
    cudaGetSymbolAddress((void**)&w2h, g_w2_hi);
    cudaGetSymbolAddress((void**)&w2l, g_w2_lo);

    cudaFuncSetAttribute(bf16x3_gemm,
                         cudaFuncAttributeMaxDynamicSharedMemorySize, GEMM_SMEM);

    // 1) splits
    {
        int n4 = MLX * CCX / 4;
        split_kernel<<<(n4 + 255) / 256, 256>>>(x, xh, xl, n4);
    }
    {
        dim3 grid(KK / 32, (3 * CCX) / 32);
        splitT_kernel<<<grid, dim3(32, 8)>>>(qkv_w, w1h, w1l, 3 * CCX);
    }
    {
        dim3 grid(KK / 32, CCX / 32);
        splitT_kernel<<<grid, dim3(32, 8)>>>(proj_w, w2h, w2l, CCX);
    }

    // 2) QKV GEMM: [16384,512] x [1536,512]^T -> g_qkv
    {
        dim3 grid((3 * CCX) / 128, MLX / 128);
        bf16x3_gemm<<<grid, 256, GEMM_SMEM>>>(xh, xl, w1h, w1l, qkv_b, qkv, 3 * CCX);
    }

    // 3) attention (writes split bf16 output)
    {
        dim3 grid(LLX / LT, HHX, BBX);
        natten1d_kernel<<<grid, 128>>>(rpb);
    }

    // 4) proj GEMM: [16384,512] x [512,512]^T -> out
    {
        dim3 grid(CCX / 128, MLX / 128);
        bf16x3_gemm<<<grid, 256, GEMM_SMEM>>>(ah, al, w2h, w2l, proj_b, out, CCX);
    }
}

// round 6
// speedup vs baseline: 1.9865x; 1.0269x over previous
#include <cuda_runtime.h>
#include <cuda_bf16.h>
#include <cstdint>
#include <math.h>

// Problem constants
#define BBX 4
#define LLX 4096
#define CCX 512
#define HHX 16
#define HDX 32
#define KWX 13
#define KHX 6
#define NRPBX 25
#define MLX (BBX*LLX)          // 16384
#define KK  512

// ---------------------------------------------------------------------------
// Global scratch
// ---------------------------------------------------------------------------
__device__ float g_qkv[(size_t)MLX * (3 * CCX)];
__device__ __nv_bfloat16 g_xa_hi[(size_t)MLX * CCX];
__device__ __nv_bfloat16 g_xa_lo[(size_t)MLX * CCX];
__device__ __nv_bfloat16 g_at_hi[(size_t)MLX * CCX];
__device__ __nv_bfloat16 g_at_lo[(size_t)MLX * CCX];
__device__ __nv_bfloat16 g_w1_hi[(size_t)(3*CCX) * CCX];
__device__ __nv_bfloat16 g_w1_lo[(size_t)(3*CCX) * CCX];
__device__ __nv_bfloat16 g_w2_hi[(size_t)CCX * CCX];
__device__ __nv_bfloat16 g_w2_lo[(size_t)CCX * CCX];

// ---------------------------------------------------------------------------
// Helpers
// ---------------------------------------------------------------------------
__device__ __forceinline__ uint32_t sptr(const void* p) {
    return (uint32_t)__cvta_generic_to_shared(p);
}
__device__ __forceinline__ void cp16(uint32_t s, const void* g) {
    asm volatile("cp.async.cg.shared.global [%0], [%1], 16;\n" :: "r"(s), "l"(g));
}
__device__ __forceinline__ void cp_commit() {
    asm volatile("cp.async.commit_group;\n" ::: "memory");
}
__device__ __forceinline__ void cp_wait0() {
    asm volatile("cp.async.wait_group 0;\n" ::: "memory");
}
__device__ __forceinline__ void mma_bf16(float* c, const uint32_t* a, const uint32_t* b) {
    asm volatile(
        "mma.sync.aligned.m16n8k16.row.col.f32.bf16.bf16.f32 "
        "{%0,%1,%2,%3}, {%4,%5,%6,%7}, {%8,%9}, {%0,%1,%2,%3};\n"
        : "+f"(c[0]), "+f"(c[1]), "+f"(c[2]), "+f"(c[3])
        : "r"(a[0]), "r"(a[1]), "r"(a[2]), "r"(a[3]), "r"(b[0]), "r"(b[1]));
}
__device__ __forceinline__ void bf16split(float x, __nv_bfloat16& h, __nv_bfloat16& l) {
    h = __float2bfloat16(x);
    l = __float2bfloat16(x - __bfloat162float(h));
}

// ---------------------------------------------------------------------------
// bf16x3 GEMM, warp tile 64x64: C[M,N] = (Ahi+Alo)[M,512] x ((Bhi+Blo)[N,512])^T + bias
// 128x128 CTA tile, 128 threads (4 warps, 2x2), BK=32 bf16, 2-stage cp.async.
// ---------------------------------------------------------------------------
#define RSTR 40                      // bf16 row stride (80 B, conflict-free, 16B-aligned)
#define TILE_B (128u * RSTR * 2u)    // 10240 B
#define STAGE_B (4u * TILE_B)        // 40960 B
#define GEMM_SMEM (2u * STAGE_B)     // 81920 B

__global__ __launch_bounds__(128, 2)
void bf16x3_gemm(const __nv_bfloat16* __restrict__ Ahi, const __nv_bfloat16* __restrict__ Alo,
                 const __nv_bfloat16* __restrict__ Bhi, const __nv_bfloat16* __restrict__ Blo,
                 const float* __restrict__ bias, float* __restrict__ C, int N)
{
    extern __shared__ char smem[];

    const int tid  = threadIdx.x;
    const int warp = tid >> 5;     // 0..3
    const int lane = tid & 31;
    const int wm   = warp & 1;     // 64-row slab
    const int wn   = warp >> 1;    // 64-col slab
    const int gid  = lane >> 2;    // 0..7
    const int tg   = lane & 3;     // 0..3

    const int bm0 = blockIdx.y * 128;
    const int bn0 = blockIdx.x * 128;

    // loader: warp w loads operand w (0=Ah 1=Al 2=Bh 3=Bl), 128 rows x 64 B
    const __nv_bfloat16* lsrc = (warp == 0) ? Ahi : (warp == 1) ? Alo
                              : (warp == 2) ? Bhi : Blo;
    const int lrow0 = (warp < 2) ? bm0 : bn0;
    const __nv_bfloat16* gsrc = lsrc + (size_t)lrow0 * KK;
    const uint32_t tbase = sptr(smem) + (uint32_t)warp * TILE_B;

    #define LOADCHUNK(c, bufb) do { \
        const __nv_bfloat16* gp0 = gsrc + (c) * 32; \
        const uint32_t sm0 = tbase + (bufb) * STAGE_B; \
        _Pragma("unroll") \
        for (int i_ = 0; i_ < 16; i_++) { \
            int u_ = i_ * 32 + lane; \
            int row_ = u_ >> 2; \
            int c16_ = u_ & 3; \
            cp16(sm0 + (uint32_t)(row_ * (RSTR * 2) + c16_ * 16), \
                 gp0 + (size_t)row_ * KK + c16_ * 8); \
        } \
        cp_commit(); \
    } while (0)

    float acc[4][8][4];
    #pragma unroll
    for (int mt = 0; mt < 4; mt++)
        #pragma unroll
        for (int nt = 0; nt < 8; nt++)
            #pragma unroll
            for (int c = 0; c < 4; c++) acc[mt][nt][c] = 0.f;

    const int nT = KK / 32;          // 16

    LOADCHUNK(0, 0);

    for (int t = 0; t < nT; t++) {
        cp_wait0();
        __syncthreads();
        const int cur = t & 1;

        if (t + 1 < nT) LOADCHUNK(t + 1, cur ^ 1);

        const char* stage = smem + cur * STAGE_B;
        const char* pAh = stage;
        const char* pAl = stage + TILE_B;
        const char* pBh = stage + 2 * TILE_B;
        const char* pBl = stage + 3 * TILE_B;

        #pragma unroll
        for (int ks = 0; ks < 2; ks++) {
            const int kb = ks * 32 + tg * 4;

            uint32_t bh[8][2], bl[8][2];
            #pragma unroll
            for (int nt = 0; nt < 8; nt++) {
                const int col = wn * 64 + nt * 8 + gid;
                const int o = col * (RSTR * 2) + kb;
                bh[nt][0] = *(const uint32_t*)(pBh + o);
                bh[nt][1] = *(const uint32_t*)(pBh + o + 16);
                bl[nt][0] = *(const uint32_t*)(pBl + o);
                bl[nt][1] = *(const uint32_t*)(pBl + o + 16);
            }

            #pragma unroll
            for (int mt = 0; mt < 4; mt++) {
                const int r0 = (wm * 64 + mt * 16 + gid) * (RSTR * 2) + kb;
                const int r1 = r0 + 8 * (RSTR * 2);
                uint32_t ah[4], al[4];
                ah[0] = *(const uint32_t*)(pAh + r0);
                ah[1] = *(const uint32_t*)(pAh + r1);
                ah[2] = *(const uint32_t*)(pAh + r0 + 16);
                ah[3] = *(const uint32_t*)(pAh + r1 + 16);
                al[0] = *(const uint32_t*)(pAl + r0);
                al[1] = *(const uint32_t*)(pAl + r1);
                al[2] = *(const uint32_t*)(pAl + r0 + 16);
                al[3] = *(const uint32_t*)(pAl + r1 + 16);

                #pragma unroll
                for (int nt = 0; nt < 8; nt++) {
                    mma_bf16(acc[mt][nt], ah, bh[nt]);   // hi*hi
                    mma_bf16(acc[mt][nt], ah, bl[nt]);   // hi*lo
                    mma_bf16(acc[mt][nt], al, bh[nt]);   // lo*hi
                }
            }
        }
        __syncthreads();
    }
    #undef LOADCHUNK

    // epilogue
    #pragma unroll
    for (int nt = 0; nt < 8; nt++) {
        const int col = bn0 + wn * 64 + nt * 8 + tg * 2;
        const float2 bv = *(const float2*)(bias + col);
        #pragma unroll
        for (int mt = 0; mt < 4; mt++) {
            const int r0 = bm0 + wm * 64 + mt * 16 + gid;
            float2 o0 = make_float2(acc[mt][nt][0] + bv.x, acc[mt][nt][1] + bv.y);
            float2 o1 = make_float2(acc[mt][nt][2] + bv.x, acc[mt][nt][3] + bv.y);
            *(float2*)(C + (size_t)r0 * N + col)       = o0;
            *(float2*)(C + (size_t)(r0 + 8) * N + col) = o1;
        }
    }
}

// ---------------------------------------------------------------------------
// Elementwise split to bf16 hi/lo
// ---------------------------------------------------------------------------
__global__ __launch_bounds__(256)
void split_kernel(const float* __restrict__ in, __nv_bfloat16* __restrict__ hi,
                  __nv_bfloat16* __restrict__ lo, int n4)
{
    int i = blockIdx.x * 256 + threadIdx.x;
    if (i >= n4) return;
    float4 v = ((const float4*)in)[i];
    __nv_bfloat16 h0, h1, h2, h3, l0, l1, l2, l3;
    bf16split(v.x, h0, l0); bf16split(v.y, h1, l1);
    bf16split(v.z, h2, l2); bf16split(v.w, h3, l3);
    __nv_bfloat162 hp0 = __nv_bfloat162(h0, h1), hp1 = __nv_bfloat162(h2, h3);
    __nv_bfloat162 lp0 = __nv_bfloat162(l0, l1), lp1 = __nv_bfloat162(l2, l3);
    ((uint2*)hi)[i] = make_uint2(*(uint32_t*)&hp0, *(uint32_t*)&hp1);
    ((uint2*)lo)[i] = make_uint2(*(uint32_t*)&lp0, *(uint32_t*)&lp1);
}

// ---------------------------------------------------------------------------
// Transpose + split: w[512, Ndim] -> hi/lo [Ndim, 512] bf16
// ---------------------------------------------------------------------------
__global__ __launch_bounds__(256)
void splitT_kernel(const float* __restrict__ w, __nv_bfloat16* __restrict__ hi,
                   __nv_bfloat16* __restrict__ lo, int Ndim)
{
    __shared__ float t[32][33];
    const int k0 = blockIdx.x * 32;
    const int n0 = blockIdx.y * 32;
    const int tx = threadIdx.x, ty = threadIdx.y;
    #pragma unroll
    for (int r = 0; r < 32; r += 8)
        t[ty + r][tx] = w[(size_t)(k0 + ty + r) * Ndim + n0 + tx];
    __syncthreads();
    #pragma unroll
    for (int r = 0; r < 32; r += 8) {
        float v = t[tx][ty + r];
        __nv_bfloat16 h, l;
        bf16split(v, h, l);
        const size_t idx = (size_t)(n0 + ty + r) * KK + k0 + tx;
        hi[idx] = h;
        lo[idx] = l;
    }
}

// ---------------------------------------------------------------------------
// Neighborhood attention: thread-per-l, stride-33 smem, writes bf16 split out
// ---------------------------------------------------------------------------
#define LT 128
#define WR (LT + KWX - 1)       // 140
#define SSTR 33

__global__ __launch_bounds__(128)
void natten1d_kernel(const float* __restrict__ rpb)
{
    __shared__ float sk[WR * SSTR];
    __shared__ float sv[WR * SSTR];
    __shared__ float srpb[NRPBX];

    const int tid  = threadIdx.x;
    const int warp = tid >> 5;
    const int lane = tid & 31;
    const int l0 = blockIdx.x * LT;
    const int h  = blockIdx.y;
    const int b  = blockIdx.z;
    const int base = l0 - KHX;

    const float* qb = g_qkv + (size_t)b * LLX * (3 * CCX) + h * HDX;
    const float* kb = qb + CCX;
    const float* vb = qb + 2 * CCX;

    if (tid < NRPBX) srpb[tid] = rpb[h * NRPBX + tid];

    for (int r = warp; r < WR; r += 4) {
        const int gr = base + r;
        if (gr >= 0 && gr < LLX) {
            sk[r * SSTR + lane] = kb[(size_t)gr * (3 * CCX) + lane];
            sv[r * SSTR + lane] = vb[(size_t)gr * (3 * CCX) + lane];
        }
    }
    __syncthreads();

    const int l = l0 + tid;
    int ni = l - KHX;
    if (ni < 0) ni = 0;
    if (ni > LLX - KWX) ni = LLX - KWX;
    const int roff = ni - l + (KWX - 1);
    const int s0 = ni - base;

    const float scale = 0.17677669529663687f;
    float q[HDX];
    {
        const float* qp = qb + (size_t)l * (3 * CCX);
        #pragma unroll
        for (int d4 = 0; d4 < HDX; d4 += 4) {
            float4 v = *(const float4*)(qp + d4);
            q[d4 + 0] = v.x * scale; q[d4 + 1] = v.y * scale;
            q[d4 + 2] = v.z * scale; q[d4 + 3] = v.w * scale;
        }
    }

    float sc[KWX];
    float smax = -1e30f;
    #pragma unroll
    for (int j = 0; j < KWX; j++) {
        const float* kr = &sk[(s0 + j) * SSTR];
        float s = 0.f;
        #pragma unroll
        for (int d = 0; d < HDX; d++) s = fmaf(q[d], kr[d], s);
        s += srpb[roff + j];
        sc[j] = s;
        smax = fmaxf(smax, s);
    }
    float ssum = 0.f;
    #pragma unroll
    for (int j = 0; j < KWX; j++) {
        sc[j] = __expf(sc[j] - smax);
        ssum += sc[j];
    }
    const float inv = 1.f / ssum;

    float acc[HDX];
    #pragma unroll
    for (int d = 0; d < HDX; d++) acc[d] = 0.f;
    #pragma unroll
    for (int j = 0; j < KWX; j++) {
        const float* vr = &sv[(s0 + j) * SSTR];
        const float p = sc[j];
        #pragma unroll
        for (int d = 0; d < HDX; d++) acc[d] = fmaf(p, vr[d], acc[d]);
    }

    __nv_bfloat16* oh = g_at_hi + (size_t)(b * LLX + l) * CCX + h * HDX;
    __nv_bfloat16* ol = g_at_lo + (size_t)(b * LLX + l) * CCX + h * HDX;
    #pragma unroll
    for (int d2 = 0; d2 < HDX; d2 += 2) {
        __nv_bfloat16 h0, h1, l0b, l1b;
        bf16split(acc[d2 + 0] * inv, h0, l0b);
        bf16split(acc[d2 + 1] * inv, h1, l1b);
        __nv_bfloat162 hp = __nv_bfloat162(h0, h1);
        __nv_bfloat162 lp = __nv_bfloat162(l0b, l1b);
        *(uint32_t*)(oh + d2) = *(uint32_t*)&hp;
        *(uint32_t*)(ol + d2) = *(uint32_t*)&lp;
    }
}

// ---------------------------------------------------------------------------
extern "C" void kernel_launch(void* const* d_in, const int* in_sizes, int n_in,
                              void* d_out, int out_size)
{
    const float* x      = (const float*)d_in[0];
    const float* qkv_w  = (const float*)d_in[1];
    const float* qkv_b  = (const float*)d_in[2];
    const float* rpb    = (const float*)d_in[3];
    const float* proj_w = (const float*)d_in[4];
    const float* proj_b = (const float*)d_in[5];
    float* out = (float*)d_out;

    float* qkv;
    __nv_bfloat16 *xh, *xl, *ah, *al, *w1h, *w1l, *w2h, *w2l;
    cudaGetSymbolAddress((void**)&qkv, g_qkv);
    cudaGetSymbolAddress((void**)&xh,  g_xa_hi);
    cudaGetSymbolAddress((void**)&xl,  g_xa_lo);
    cudaGetSymbolAddress((void**)&ah,  g_at_hi);
    cudaGetSymbolAddress((void**)&al,  g_at_lo);
    cudaGetSymbolAddress((void**)&w1h, g_w1_hi);
    cudaGetSymbolAddress((void**)&w1l, g_w1_lo);
    cudaGetSymbolAddress((void**)&w2h, g_w2_hi);
    cudaGetSymbolAddress((void**)&w2l, g_w2_lo);

    cudaFuncSetAttribute(bf16x3_gemm,
                         cudaFuncAttributeMaxDynamicSharedMemorySize, GEMM_SMEM);

    // 1) splits
    {
        int n4 = MLX * CCX / 4;
        split_kernel<<<(n4 + 255) / 256, 256>>>(x, xh, xl, n4);
    }
    {
        dim3 grid(KK / 32, (3 * CCX) / 32);
        splitT_kernel<<<grid, dim3(32, 8)>>>(qkv_w, w1h, w1l, 3 * CCX);
    }
    {
        dim3 grid(KK / 32, CCX / 32);
        splitT_kernel<<<grid, dim3(32, 8)>>>(proj_w, w2h, w2l, CCX);
    }

    // 2) QKV GEMM
    {
        dim3 grid((3 * CCX) / 128, MLX / 128);
        bf16x3_gemm<<<grid, 128, GEMM_SMEM>>>(xh, xl, w1h, w1l, qkv_b, qkv, 3 * CCX);
    }

    // 3) attention
    {
        dim3 grid(LLX / LT, HHX, BBX);
        natten1d_kernel<<<grid, 128>>>(rpb);
    }

    // 4) proj GEMM
    {
        dim3 grid(CCX / 128, MLX / 128);
        bf16x3_gemm<<<grid, 128, GEMM_SMEM>>>(ah, al, w2h, w2l, proj_b, out, CCX);
    }
}